// round 12
// baseline (speedup 1.0000x reference)
#include <cuda_runtime.h>

// ============================================================================
// SpectralMoEHeads: out[bt, h*64+o] = sum_k S[bt,k] * sum_i x[bt,h*64+i]*W[h,k,i,o]
//   S[bt,k] = phi[bt%2048, k] + sum_i x[bt,i]*diag[k,i]
//
// R11 = R7 skeleton (x->tf32 once, unscaled Y chains, fold S after each chunk)
//  + prep kernel packs W into per-(h,chunk) FRAGMENT ORDER -> mainloop B loads
//    are 4x LDS.128 per nt-iter (was 16x LDS.32), cp.async is a linear copy.
//  + 4-buffer W ring, prefetch issued right after the single per-chunk barrier
//    (was 2 barriers/chunk).
//  + ring buffers 2,3 overlay the dead x_s region (xf regs loaded before loop).
// ============================================================================

__device__ float g_scores[8192 * 8];
__device__ float4 wpack4[128 * 1024];   // [h*8+chunk][1024 float4] = 2 MB

__device__ __forceinline__ unsigned f2tf32(float f) {
    unsigned u;
    asm("cvt.rna.tf32.f32 %0, %1;" : "=r"(u) : "f"(f));
    return u;
}

__device__ __forceinline__ void mma_tf32_acc(float& c0, float& c1, float& c2, float& c3,
                                             unsigned a0, unsigned a1, unsigned a2, unsigned a3,
                                             unsigned b0, unsigned b1) {
    asm volatile(
        "mma.sync.aligned.m16n8k8.row.col.f32.tf32.tf32.f32 "
        "{%0,%1,%2,%3}, {%4,%5,%6,%7}, {%8,%9}, {%0,%1,%2,%3};\n"
        : "+f"(c0), "+f"(c1), "+f"(c2), "+f"(c3)
        : "r"(a0), "r"(a1), "r"(a2), "r"(a3), "r"(b0), "r"(b1));
}

__device__ __forceinline__ void mma_tf32_set(float& d0, float& d1, float& d2, float& d3,
                                             unsigned a0, unsigned a1, unsigned a2, unsigned a3,
                                             unsigned b0, unsigned b1) {
    asm volatile(
        "mma.sync.aligned.m16n8k8.row.col.f32.tf32.tf32.f32 "
        "{%0,%1,%2,%3}, {%4,%5,%6,%7}, {%8,%9}, {%10,%11,%12,%13};\n"
        : "=f"(d0), "=f"(d1), "=f"(d2), "=f"(d3)
        : "r"(a0), "r"(a1), "r"(a2), "r"(a3), "r"(b0), "r"(b1),
          "f"(0.f), "f"(0.f), "f"(0.f), "f"(0.f));
}

__device__ __forceinline__ void cp_async16(unsigned dst_smem, const void* src) {
    asm volatile("cp.async.cg.shared.global [%0], [%1], 16;\n"
                 :: "r"(dst_smem), "l"(src) : "memory");
}
__device__ __forceinline__ void cp_commit() {
    asm volatile("cp.async.commit_group;\n" ::: "memory");
}
template <int N>
__device__ __forceinline__ void cp_wait() {
    asm volatile("cp.async.wait_group %0;\n" :: "n"(N) : "memory");
}

// ---------------------------------------------------------------------------
// Kernel 0: pack W into fragment order.
// Per (h, chunk k): layout [wn(2)][nt(4)][lane(32)][16 f32], where the 16 f32
// for a lane are j = it*2 + p :  W[h,k][ i = it*8 + tig + p*4 ][ o = wn*32 + nt*8 + gid ]
// (gid = lane>>2, tig = lane&3). One 64B segment per (thread) -> cp.async linear.
// ---------------------------------------------------------------------------
__global__ __launch_bounds__(256) void prep_w_kernel(const float* __restrict__ w)
{
    __shared__ float tile[4096];           // W[h,k][i][o] : 64 x 64
    const int b   = blockIdx.x;            // 0..127 = h*8 + k
    const int tid = threadIdx.x;

    const float4* src = (const float4*)(w + (size_t)b * 4096);
#pragma unroll
    for (int it = 0; it < 4; ++it)
        ((float4*)tile)[tid + it * 256] = src[tid + it * 256];
    __syncthreads();

    const int wn   = tid >> 7;
    const int nt   = (tid >> 5) & 3;
    const int lane = tid & 31;
    const int gid  = lane >> 2;
    const int tig  = lane & 3;
    const int o    = wn * 32 + nt * 8 + gid;

#pragma unroll
    for (int q = 0; q < 4; ++q) {
        float v[4];
#pragma unroll
        for (int jj = 0; jj < 4; ++jj) {
            int j  = q * 4 + jj;
            int it = j >> 1, p = j & 1;
            v[jj] = tile[(it * 8 + tig + p * 4) * 64 + o];
        }
        wpack4[(size_t)b * 1024 + tid * 4 + q] =
            make_float4(v[0], v[1], v[2], v[3]);
    }
}

// ---------------------------------------------------------------------------
// Kernel 1: scores (unchanged; near its DRAM floor)
// ---------------------------------------------------------------------------
__global__ __launch_bounds__(256) void scores_kernel(
    const float* __restrict__ x, const float* __restrict__ diag,
    const float* __restrict__ phi)
{
    __shared__ float4 diag_s[8 * 256];

    const int tid = threadIdx.x;
    for (int i = tid; i < 2048; i += 256) diag_s[i] = ((const float4*)diag)[i];
    __syncthreads();

    const int lane = tid & 31;
    const int w    = tid >> 5;
    const int t0   = (blockIdx.x * 8 + w) * 4;

    float acc[4][8];
#pragma unroll
    for (int t = 0; t < 4; ++t)
#pragma unroll
        for (int k = 0; k < 8; ++k) acc[t][k] = 0.f;

#pragma unroll
    for (int c = 0; c < 8; ++c) {
        float4 dv[8];
#pragma unroll
        for (int k = 0; k < 8; ++k) dv[k] = diag_s[k * 256 + c * 32 + lane];
#pragma unroll
        for (int t = 0; t < 4; ++t) {
            float4 xv = ((const float4*)x)[(size_t)(t0 + t) * 256 + c * 32 + lane];
#pragma unroll
            for (int k = 0; k < 8; ++k) {
                acc[t][k] = fmaf(xv.x, dv[k].x, acc[t][k]);
                acc[t][k] = fmaf(xv.y, dv[k].y, acc[t][k]);
                acc[t][k] = fmaf(xv.z, dv[k].z, acc[t][k]);
                acc[t][k] = fmaf(xv.w, dv[k].w, acc[t][k]);
            }
        }
    }

#pragma unroll
    for (int t = 0; t < 4; ++t)
#pragma unroll
        for (int k = 0; k < 8; ++k) {
            float v = acc[t][k];
            v += __shfl_xor_sync(0xffffffffu, v, 16);
            v += __shfl_xor_sync(0xffffffffu, v, 8);
            v += __shfl_xor_sync(0xffffffffu, v, 4);
            v += __shfl_xor_sync(0xffffffffu, v, 2);
            v += __shfl_xor_sync(0xffffffffu, v, 1);
            acc[t][k] = v;
        }

    if (lane == 0) {
#pragma unroll
        for (int t = 0; t < 4; ++t) {
            const int bt = t0 + t;
            float4 p0 = ((const float4*)phi)[(bt & 2047) * 2];
            float4 p1 = ((const float4*)phi)[(bt & 2047) * 2 + 1];
            float4 r0 = make_float4(acc[t][0] + p0.x, acc[t][1] + p0.y,
                                    acc[t][2] + p0.z, acc[t][3] + p0.w);
            float4 r1 = make_float4(acc[t][4] + p1.x, acc[t][5] + p1.y,
                                    acc[t][6] + p1.z, acc[t][7] + p1.w);
            ((float4*)g_scores)[bt * 2]     = r0;
            ((float4*)g_scores)[bt * 2 + 1] = r1;
        }
    }
}

// ---------------------------------------------------------------------------
// Kernel 2: main. CTA = (128-token tile, head), 256 threads = 8 warps
// (4m x 2n), warp tile 32x32, mma m16n8k8 tf32.
// smem floats: S_s[1152] | buf0[4096] | buf1[4096] | x_s[8704] (bufs 2,3 overlay)
// ---------------------------------------------------------------------------
#define SS_STRIDE   9
#define SMEM_SS     0
#define SMEM_BUF0   1152
#define SMEM_XS     (1152 + 2 * 4096)          // = 9344 (bufs 2,3 live here)
#define XS_STRIDE   68
#define MAIN_SMEM_FLOATS (SMEM_XS + 128 * XS_STRIDE)   // 18048 floats = 72192 B

__global__ __launch_bounds__(256, 2) void spectral_main_kernel(
    const float* __restrict__ x, float* __restrict__ out)
{
    extern __shared__ float sm[];
    float* S_s = sm + SMEM_SS;
    float* x_s = sm + SMEM_XS;
    const unsigned smem_u32 = (unsigned)__cvta_generic_to_shared(sm);
    const unsigned buf_base = smem_u32 + SMEM_BUF0 * 4;   // buf i at + i*16384 B

    const int tid  = threadIdx.x;
    const int h    = blockIdx.y;
    const int bt0  = blockIdx.x * 128;

    const int lane = tid & 31;
    const int wid  = tid >> 5;
    const int gid  = lane >> 2;   // 0..7
    const int tig  = lane & 3;    // 0..3
    const int wm   = wid & 3;     // m warp coord (x32)
    const int wn   = wid >> 2;    // n warp coord (x32)

    const float4* wsrc = wpack4 + (size_t)h * 8192;   // 8 chunks x 1024 float4

    // ---- prologue: cp.async W chunks 0,1 into bufs 0,1 ----
#pragma unroll
    for (int c = 0; c < 2; ++c) {
        const float4* src = wsrc + c * 1024 + tid * 4;
        unsigned d = buf_base + c * 16384 + tid * 64;
        cp_async16(d,      src);
        cp_async16(d + 16, src + 1);
        cp_async16(d + 32, src + 2);
        cp_async16(d + 48, src + 3);
        cp_commit();
    }

    // ---- stage x tile (128 x 64) into x_s (bufs 2,3 region — not yet used) ----
#pragma unroll
    for (int j = 0; j < 8; ++j) {
        int idx = tid + j * 256;
        int r = idx >> 4, c4 = idx & 15;
        float4 v = ((const float4*)x)[(size_t)(bt0 + r) * 256 + h * 16 + c4];
        float* d = x_s + r * XS_STRIDE + c4 * 4;
        d[0] = v.x; d[1] = v.y; d[2] = v.z; d[3] = v.w;
    }
    // ---- stage scores ----
#pragma unroll
    for (int j = 0; j < 4; ++j) {
        int idx = tid + j * 256;
        int r = idx >> 3, k = idx & 7;
        S_s[r * SS_STRIDE + k] = g_scores[(bt0 + r) * 8 + k];
    }
    __syncthreads();

    // ---- x fragments -> tf32 once ----
    unsigned xf[2][8][4];
#pragma unroll
    for (int mt = 0; mt < 2; ++mt) {
        const int t0 = wm * 32 + mt * 16 + gid;
        const int t1 = t0 + 8;
#pragma unroll
        for (int it = 0; it < 8; ++it) {
            const int i0 = it * 8 + tig;
            xf[mt][it][0] = f2tf32(x_s[t0 * XS_STRIDE + i0]);
            xf[mt][it][1] = f2tf32(x_s[t1 * XS_STRIDE + i0]);
            xf[mt][it][2] = f2tf32(x_s[t0 * XS_STRIDE + i0 + 4]);
            xf[mt][it][3] = f2tf32(x_s[t1 * XS_STRIDE + i0 + 4]);
        }
    }
    __syncthreads();   // all warps done reading x_s before buf2/3 prefetch

    float acc[2][4][4];
#pragma unroll
    for (int mt = 0; mt < 2; ++mt)
#pragma unroll
        for (int nt = 0; nt < 4; ++nt)
#pragma unroll
            for (int r = 0; r < 4; ++r) acc[mt][nt][r] = 0.f;

    // per-thread B base within a buffer: [(wn*4+nt)*32 + lane] * 64 bytes
    const unsigned bthread = ((unsigned)(wn * 4) * 32 + lane) * 64;

#pragma unroll 1
    for (int k = 0; k < 8; ++k) {
        if (k < 7) cp_wait<1>(); else cp_wait<0>();
        __syncthreads();   // single barrier per chunk

        // prefetch chunk k+2 into buf (k+2)&3 (last read in chunk k-2; all
        // warps are past the barrier of chunk k, hence done with k-2's reads)
        if (k + 2 < 8) {
            const float4* src = wsrc + (k + 2) * 1024 + tid * 4;
            unsigned d = buf_base + ((k + 2) & 3) * 16384 + tid * 64;
            cp_async16(d,      src);
            cp_async16(d + 16, src + 1);
            cp_async16(d + 32, src + 2);
            cp_async16(d + 48, src + 3);
            cp_commit();
        }

        const int tb = wm * 32 + gid;
        const float s00 = S_s[(tb)      * SS_STRIDE + k];
        const float s01 = S_s[(tb + 8)  * SS_STRIDE + k];
        const float s10 = S_s[(tb + 16) * SS_STRIDE + k];
        const float s11 = S_s[(tb + 24) * SS_STRIDE + k];

        const unsigned bbuf = buf_base + (k & 3) * 16384 + bthread;

#pragma unroll
        for (int nt = 0; nt < 4; ++nt) {
            const unsigned baddr = bbuf + (unsigned)nt * (32 * 64);
            float a0c[4], a1c[4];
            uint4 bw0, bw1;

            // half 1: its 0..3  (words j = it*2 + p : {b0,b1} interleaved)
            asm volatile("ld.shared.v4.b32 {%0,%1,%2,%3}, [%4];"
                         : "=r"(bw0.x), "=r"(bw0.y), "=r"(bw0.z), "=r"(bw0.w)
                         : "r"(baddr));
            asm volatile("ld.shared.v4.b32 {%0,%1,%2,%3}, [%4];"
                         : "=r"(bw1.x), "=r"(bw1.y), "=r"(bw1.z), "=r"(bw1.w)
                         : "r"(baddr + 16));
            mma_tf32_set(a0c[0], a0c[1], a0c[2], a0c[3],
                         xf[0][0][0], xf[0][0][1], xf[0][0][2], xf[0][0][3], bw0.x, bw0.y);
            mma_tf32_set(a1c[0], a1c[1], a1c[2], a1c[3],
                         xf[1][0][0], xf[1][0][1], xf[1][0][2], xf[1][0][3], bw0.x, bw0.y);
            mma_tf32_acc(a0c[0], a0c[1], a0c[2], a0c[3],
                         xf[0][1][0], xf[0][1][1], xf[0][1][2], xf[0][1][3], bw0.z, bw0.w);
            mma_tf32_acc(a1c[0], a1c[1], a1c[2], a1c[3],
                         xf[1][1][0], xf[1][1][1], xf[1][1][2], xf[1][1][3], bw0.z, bw0.w);
            mma_tf32_acc(a0c[0], a0c[1], a0c[2], a0c[3],
                         xf[0][2][0], xf[0][2][1], xf[0][2][2], xf[0][2][3], bw1.x, bw1.y);
            mma_tf32_acc(a1c[0], a1c[1], a1c[2], a1c[3],
                         xf[1][2][0], xf[1][2][1], xf[1][2][2], xf[1][2][3], bw1.x, bw1.y);
            mma_tf32_acc(a0c[0], a0c[1], a0c[2], a0c[3],
                         xf[0][3][0], xf[0][3][1], xf[0][3][2], xf[0][3][3], bw1.z, bw1.w);
            mma_tf32_acc(a1c[0], a1c[1], a1c[2], a1c[3],
                         xf[1][3][0], xf[1][3][1], xf[1][3][2], xf[1][3][3], bw1.z, bw1.w);

            // half 2: its 4..7
            asm volatile("ld.shared.v4.b32 {%0,%1,%2,%3}, [%4];"
                         : "=r"(bw0.x), "=r"(bw0.y), "=r"(bw0.z), "=r"(bw0.w)
                         : "r"(baddr + 32));
            asm volatile("ld.shared.v4.b32 {%0,%1,%2,%3}, [%4];"
                         : "=r"(bw1.x), "=r"(bw1.y), "=r"(bw1.z), "=r"(bw1.w)
                         : "r"(baddr + 48));
            mma_tf32_acc(a0c[0], a0c[1], a0c[2], a0c[3],
                         xf[0][4][0], xf[0][4][1], xf[0][4][2], xf[0][4][3], bw0.x, bw0.y);
            mma_tf32_acc(a1c[0], a1c[1], a1c[2], a1c[3],
                         xf[1][4][0], xf[1][4][1], xf[1][4][2], xf[1][4][3], bw0.x, bw0.y);
            mma_tf32_acc(a0c[0], a0c[1], a0c[2], a0c[3],
                         xf[0][5][0], xf[0][5][1], xf[0][5][2], xf[0][5][3], bw0.z, bw0.w);
            mma_tf32_acc(a1c[0], a1c[1], a1c[2], a1c[3],
                         xf[1][5][0], xf[1][5][1], xf[1][5][2], xf[1][5][3], bw0.z, bw0.w);
            mma_tf32_acc(a0c[0], a0c[1], a0c[2], a0c[3],
                         xf[0][6][0], xf[0][6][1], xf[0][6][2], xf[0][6][3], bw1.x, bw1.y);
            mma_tf32_acc(a1c[0], a1c[1], a1c[2], a1c[3],
                         xf[1][6][0], xf[1][6][1], xf[1][6][2], xf[1][6][3], bw1.x, bw1.y);
            mma_tf32_acc(a0c[0], a0c[1], a0c[2], a0c[3],
                         xf[0][7][0], xf[0][7][1], xf[0][7][2], xf[0][7][3], bw1.z, bw1.w);
            mma_tf32_acc(a1c[0], a1c[1], a1c[2], a1c[3],
                         xf[1][7][0], xf[1][7][1], xf[1][7][2], xf[1][7][3], bw1.z, bw1.w);

            // fold S into master accumulators
            acc[0][nt][0] = fmaf(s00, a0c[0], acc[0][nt][0]);
            acc[0][nt][1] = fmaf(s00, a0c[1], acc[0][nt][1]);
            acc[0][nt][2] = fmaf(s01, a0c[2], acc[0][nt][2]);
            acc[0][nt][3] = fmaf(s01, a0c[3], acc[0][nt][3]);
            acc[1][nt][0] = fmaf(s10, a1c[0], acc[1][nt][0]);
            acc[1][nt][1] = fmaf(s10, a1c[1], acc[1][nt][1]);
            acc[1][nt][2] = fmaf(s11, a1c[2], acc[1][nt][2]);
            acc[1][nt][3] = fmaf(s11, a1c[3], acc[1][nt][3]);
        }
    }

    // ---- epilogue: fp32 store ----
#pragma unroll
    for (int mt = 0; mt < 2; ++mt) {
        const int t0 = bt0 + wm * 32 + mt * 16 + gid;
#pragma unroll
        for (int nt = 0; nt < 4; ++nt) {
            const int o = h * 64 + wn * 32 + nt * 8 + tig * 2;
            *(float2*)(out + (size_t)t0 * 1024 + o) =
                make_float2(acc[mt][nt][0], acc[mt][nt][1]);
            *(float2*)(out + (size_t)(t0 + 8) * 1024 + o) =
                make_float2(acc[mt][nt][2], acc[mt][nt][3]);
        }
    }
}

// ---------------------------------------------------------------------------
extern "C" void kernel_launch(void* const* d_in, const int* in_sizes, int n_in,
                              void* d_out, int out_size) {
    const float* x    = (const float*)d_in[0];   // [4,2048,1024]
    const float* wgt  = (const float*)d_in[1];   // [16,8,64,64]
    const float* diag = (const float*)d_in[2];   // [8,1024]
    const float* phi  = (const float*)d_in[3];   // [2048,8]
    float* out = (float*)d_out;                  // [4,2048,1024]

    const int main_smem = MAIN_SMEM_FLOATS * 4;
    cudaFuncSetAttribute(spectral_main_kernel,
                         cudaFuncAttributeMaxDynamicSharedMemorySize, main_smem);

    prep_w_kernel<<<128, 256>>>(wgt);
    scores_kernel<<<256, 256>>>(x, diag, phi);
    spectral_main_kernel<<<dim3(64, 16), 256, main_smem>>>(x, out);
}

// round 13
// speedup vs baseline: 1.3813x; 1.3813x over previous
#include <cuda_runtime.h>

// ============================================================================
// SpectralMoEHeads: out[bt, h*64+o] = sum_k S[bt,k] * sum_i x[bt,h*64+i]*W[h,k,i,o]
//   S[bt,k] = phi[bt%2048, k] + sum_i x[bt,i]*diag[k,i]
//
// R13 = R12 with the bank-conflict fix:
//   packed-W layout transposed to [wn*4+nt][q(4)][lane(32)][4 f32]
//   -> LDS.128 lane stride 16B (4-phase minimum) instead of 64B (16-way conflict).
// Kept from R12: 4-buffer W ring, single barrier/chunk, x_s overlay on bufs 2,3,
//   unscaled Y-chains (x->tf32 once) with S folded after each chunk.
// ============================================================================

__device__ float g_scores[8192 * 8];
__device__ float4 wpack4[128 * 1024];   // [h*8+chunk][1024 float4] = 2 MB

__device__ __forceinline__ unsigned f2tf32(float f) {
    unsigned u;
    asm("cvt.rna.tf32.f32 %0, %1;" : "=r"(u) : "f"(f));
    return u;
}

__device__ __forceinline__ void mma_tf32_acc(float& c0, float& c1, float& c2, float& c3,
                                             unsigned a0, unsigned a1, unsigned a2, unsigned a3,
                                             unsigned b0, unsigned b1) {
    asm volatile(
        "mma.sync.aligned.m16n8k8.row.col.f32.tf32.tf32.f32 "
        "{%0,%1,%2,%3}, {%4,%5,%6,%7}, {%8,%9}, {%0,%1,%2,%3};\n"
        : "+f"(c0), "+f"(c1), "+f"(c2), "+f"(c3)
        : "r"(a0), "r"(a1), "r"(a2), "r"(a3), "r"(b0), "r"(b1));
}

__device__ __forceinline__ void mma_tf32_set(float& d0, float& d1, float& d2, float& d3,
                                             unsigned a0, unsigned a1, unsigned a2, unsigned a3,
                                             unsigned b0, unsigned b1) {
    asm volatile(
        "mma.sync.aligned.m16n8k8.row.col.f32.tf32.tf32.f32 "
        "{%0,%1,%2,%3}, {%4,%5,%6,%7}, {%8,%9}, {%10,%11,%12,%13};\n"
        : "=f"(d0), "=f"(d1), "=f"(d2), "=f"(d3)
        : "r"(a0), "r"(a1), "r"(a2), "r"(a3), "r"(b0), "r"(b1),
          "f"(0.f), "f"(0.f), "f"(0.f), "f"(0.f));
}

__device__ __forceinline__ void cp_async16(unsigned dst_smem, const void* src) {
    asm volatile("cp.async.cg.shared.global [%0], [%1], 16;\n"
                 :: "r"(dst_smem), "l"(src) : "memory");
}
__device__ __forceinline__ void cp_commit() {
    asm volatile("cp.async.commit_group;\n" ::: "memory");
}
template <int N>
__device__ __forceinline__ void cp_wait() {
    asm volatile("cp.async.wait_group %0;\n" :: "n"(N) : "memory");
}

// ---------------------------------------------------------------------------
// Kernel 0: pack W into fragment order (conflict-free interleave).
// Per (h, chunk k): float4 index  idx4 = ((wn*4+nt)*4 + q)*32 + lane,
// holding words j = q*4..q*4+3, where j = it*2+p and the word value is
//   W[h,k][ i = it*8 + tig + p*4 ][ o = wn*32 + nt*8 + gid ]
// (gid = lane>>2, tig = lane&3).
// ---------------------------------------------------------------------------
__global__ __launch_bounds__(256) void prep_w_kernel(const float* __restrict__ w)
{
    __shared__ float tile[4096];           // W[h,k][i][o] : 64 x 64
    const int b   = blockIdx.x;            // 0..127 = h*8 + k
    const int tid = threadIdx.x;

    const float4* src = (const float4*)(w + (size_t)b * 4096);
#pragma unroll
    for (int it = 0; it < 4; ++it)
        ((float4*)tile)[tid + it * 256] = src[tid + it * 256];
    __syncthreads();

    const int grp  = tid >> 5;             // wn*4 + nt  (0..7)
    const int lane = tid & 31;
    const int gid  = lane >> 2;
    const int tig  = lane & 3;
    const int wn   = grp >> 2;
    const int nt   = grp & 3;
    const int o    = wn * 32 + nt * 8 + gid;

#pragma unroll
    for (int q = 0; q < 4; ++q) {
        float v[4];
#pragma unroll
        for (int jj = 0; jj < 4; ++jj) {
            int j  = q * 4 + jj;
            int it = j >> 1, p = j & 1;
            v[jj] = tile[(it * 8 + tig + p * 4) * 64 + o];
        }
        wpack4[(size_t)b * 1024 + (grp * 4 + q) * 32 + lane] =
            make_float4(v[0], v[1], v[2], v[3]);
    }
}

// ---------------------------------------------------------------------------
// Kernel 1: scores (unchanged; near its DRAM floor)
// ---------------------------------------------------------------------------
__global__ __launch_bounds__(256) void scores_kernel(
    const float* __restrict__ x, const float* __restrict__ diag,
    const float* __restrict__ phi)
{
    __shared__ float4 diag_s[8 * 256];

    const int tid = threadIdx.x;
    for (int i = tid; i < 2048; i += 256) diag_s[i] = ((const float4*)diag)[i];
    __syncthreads();

    const int lane = tid & 31;
    const int w    = tid >> 5;
    const int t0   = (blockIdx.x * 8 + w) * 4;

    float acc[4][8];
#pragma unroll
    for (int t = 0; t < 4; ++t)
#pragma unroll
        for (int k = 0; k < 8; ++k) acc[t][k] = 0.f;

#pragma unroll
    for (int c = 0; c < 8; ++c) {
        float4 dv[8];
#pragma unroll
        for (int k = 0; k < 8; ++k) dv[k] = diag_s[k * 256 + c * 32 + lane];
#pragma unroll
        for (int t = 0; t < 4; ++t) {
            float4 xv = ((const float4*)x)[(size_t)(t0 + t) * 256 + c * 32 + lane];
#pragma unroll
            for (int k = 0; k < 8; ++k) {
                acc[t][k] = fmaf(xv.x, dv[k].x, acc[t][k]);
                acc[t][k] = fmaf(xv.y, dv[k].y, acc[t][k]);
                acc[t][k] = fmaf(xv.z, dv[k].z, acc[t][k]);
                acc[t][k] = fmaf(xv.w, dv[k].w, acc[t][k]);
            }
        }
    }

#pragma unroll
    for (int t = 0; t < 4; ++t)
#pragma unroll
        for (int k = 0; k < 8; ++k) {
            float v = acc[t][k];
            v += __shfl_xor_sync(0xffffffffu, v, 16);
            v += __shfl_xor_sync(0xffffffffu, v, 8);
            v += __shfl_xor_sync(0xffffffffu, v, 4);
            v += __shfl_xor_sync(0xffffffffu, v, 2);
            v += __shfl_xor_sync(0xffffffffu, v, 1);
            acc[t][k] = v;
        }

    if (lane == 0) {
#pragma unroll
        for (int t = 0; t < 4; ++t) {
            const int bt = t0 + t;
            float4 p0 = ((const float4*)phi)[(bt & 2047) * 2];
            float4 p1 = ((const float4*)phi)[(bt & 2047) * 2 + 1];
            float4 r0 = make_float4(acc[t][0] + p0.x, acc[t][1] + p0.y,
                                    acc[t][2] + p0.z, acc[t][3] + p0.w);
            float4 r1 = make_float4(acc[t][4] + p1.x, acc[t][5] + p1.y,
                                    acc[t][6] + p1.z, acc[t][7] + p1.w);
            ((float4*)g_scores)[bt * 2]     = r0;
            ((float4*)g_scores)[bt * 2 + 1] = r1;
        }
    }
}

// ---------------------------------------------------------------------------
// Kernel 2: main. CTA = (128-token tile, head), 256 threads = 8 warps
// (4m x 2n), warp tile 32x32, mma m16n8k8 tf32.
// smem floats: S_s[1152] | buf0[4096] | buf1[4096] | x_s[8704] (bufs 2,3 overlay)
// ---------------------------------------------------------------------------
#define SS_STRIDE   9
#define SMEM_SS     0
#define SMEM_BUF0   1152
#define SMEM_XS     (1152 + 2 * 4096)          // = 9344 (bufs 2,3 live here)
#define XS_STRIDE   68
#define MAIN_SMEM_FLOATS (SMEM_XS + 128 * XS_STRIDE)   // 18048 floats = 72192 B

__global__ __launch_bounds__(256, 2) void spectral_main_kernel(
    const float* __restrict__ x, float* __restrict__ out)
{
    extern __shared__ float sm[];
    float* S_s = sm + SMEM_SS;
    float* x_s = sm + SMEM_XS;
    const unsigned smem_u32 = (unsigned)__cvta_generic_to_shared(sm);
    const unsigned buf_base = smem_u32 + SMEM_BUF0 * 4;   // buf i at + i*16384 B

    const int tid  = threadIdx.x;
    const int h    = blockIdx.y;
    const int bt0  = blockIdx.x * 128;

    const int lane = tid & 31;
    const int wid  = tid >> 5;
    const int gid  = lane >> 2;   // 0..7
    const int tig  = lane & 3;    // 0..3
    const int wm   = wid & 3;     // m warp coord (x32)
    const int wn   = wid >> 2;    // n warp coord (x32)

    const float4* wsrc = wpack4 + (size_t)h * 8192;   // 8 chunks x 1024 float4

    // ---- prologue: cp.async W chunks 0,1 into bufs 0,1 ----
#pragma unroll
    for (int c = 0; c < 2; ++c) {
        const float4* src = wsrc + c * 1024 + tid * 4;
        unsigned d = buf_base + c * 16384 + tid * 64;
        cp_async16(d,      src);
        cp_async16(d + 16, src + 1);
        cp_async16(d + 32, src + 2);
        cp_async16(d + 48, src + 3);
        cp_commit();
    }

    // ---- stage x tile (128 x 64) into x_s (bufs 2,3 region — not yet used) ----
#pragma unroll
    for (int j = 0; j < 8; ++j) {
        int idx = tid + j * 256;
        int r = idx >> 4, c4 = idx & 15;
        float4 v = ((const float4*)x)[(size_t)(bt0 + r) * 256 + h * 16 + c4];
        float* d = x_s + r * XS_STRIDE + c4 * 4;
        d[0] = v.x; d[1] = v.y; d[2] = v.z; d[3] = v.w;
    }
    // ---- stage scores ----
#pragma unroll
    for (int j = 0; j < 4; ++j) {
        int idx = tid + j * 256;
        int r = idx >> 3, k = idx & 7;
        S_s[r * SS_STRIDE + k] = g_scores[(bt0 + r) * 8 + k];
    }
    __syncthreads();

    // ---- x fragments -> tf32 once ----
    unsigned xf[2][8][4];
#pragma unroll
    for (int mt = 0; mt < 2; ++mt) {
        const int t0 = wm * 32 + mt * 16 + gid;
        const int t1 = t0 + 8;
#pragma unroll
        for (int it = 0; it < 8; ++it) {
            const int i0 = it * 8 + tig;
            xf[mt][it][0] = f2tf32(x_s[t0 * XS_STRIDE + i0]);
            xf[mt][it][1] = f2tf32(x_s[t1 * XS_STRIDE + i0]);
            xf[mt][it][2] = f2tf32(x_s[t0 * XS_STRIDE + i0 + 4]);
            xf[mt][it][3] = f2tf32(x_s[t1 * XS_STRIDE + i0 + 4]);
        }
    }
    __syncthreads();   // all warps done reading x_s before buf2/3 prefetch

    float acc[2][4][4];
#pragma unroll
    for (int mt = 0; mt < 2; ++mt)
#pragma unroll
        for (int nt = 0; nt < 4; ++nt)
#pragma unroll
            for (int r = 0; r < 4; ++r) acc[mt][nt][r] = 0.f;

    // per-thread B base within a buffer: group (wn*4+nt) block is 2048 B;
    // within it, q blocks of 512 B, lane stride 16 B (4-phase LDS.128).
    const unsigned bthread = (unsigned)(wn * 4) * 2048 + (unsigned)lane * 16;

#pragma unroll 1
    for (int k = 0; k < 8; ++k) {
        if (k < 7) cp_wait<1>(); else cp_wait<0>();
        __syncthreads();   // single barrier per chunk

        // prefetch chunk k+2 into buf (k+2)&3 (last read in chunk k-2; all
        // warps are past the barrier of chunk k, hence done with k-2's reads)
        if (k + 2 < 8) {
            const float4* src = wsrc + (k + 2) * 1024 + tid * 4;
            unsigned d = buf_base + ((k + 2) & 3) * 16384 + tid * 64;
            cp_async16(d,      src);
            cp_async16(d + 16, src + 1);
            cp_async16(d + 32, src + 2);
            cp_async16(d + 48, src + 3);
            cp_commit();
        }

        const int tb = wm * 32 + gid;
        const float s00 = S_s[(tb)      * SS_STRIDE + k];
        const float s01 = S_s[(tb + 8)  * SS_STRIDE + k];
        const float s10 = S_s[(tb + 16) * SS_STRIDE + k];
        const float s11 = S_s[(tb + 24) * SS_STRIDE + k];

        const unsigned bbuf = buf_base + (k & 3) * 16384 + bthread;

#pragma unroll
        for (int nt = 0; nt < 4; ++nt) {
            const unsigned baddr = bbuf + (unsigned)nt * 2048;
            float a0c[4], a1c[4];
            uint4 bw0, bw1;

            // q=0 (its 0,1) and q=1 (its 2,3)
            asm volatile("ld.shared.v4.b32 {%0,%1,%2,%3}, [%4];"
                         : "=r"(bw0.x), "=r"(bw0.y), "=r"(bw0.z), "=r"(bw0.w)
                         : "r"(baddr));
            asm volatile("ld.shared.v4.b32 {%0,%1,%2,%3}, [%4];"
                         : "=r"(bw1.x), "=r"(bw1.y), "=r"(bw1.z), "=r"(bw1.w)
                         : "r"(baddr + 512));
            mma_tf32_set(a0c[0], a0c[1], a0c[2], a0c[3],
                         xf[0][0][0], xf[0][0][1], xf[0][0][2], xf[0][0][3], bw0.x, bw0.y);
            mma_tf32_set(a1c[0], a1c[1], a1c[2], a1c[3],
                         xf[1][0][0], xf[1][0][1], xf[1][0][2], xf[1][0][3], bw0.x, bw0.y);
            mma_tf32_acc(a0c[0], a0c[1], a0c[2], a0c[3],
                         xf[0][1][0], xf[0][1][1], xf[0][1][2], xf[0][1][3], bw0.z, bw0.w);
            mma_tf32_acc(a1c[0], a1c[1], a1c[2], a1c[3],
                         xf[1][1][0], xf[1][1][1], xf[1][1][2], xf[1][1][3], bw0.z, bw0.w);
            mma_tf32_acc(a0c[0], a0c[1], a0c[2], a0c[3],
                         xf[0][2][0], xf[0][2][1], xf[0][2][2], xf[0][2][3], bw1.x, bw1.y);
            mma_tf32_acc(a1c[0], a1c[1], a1c[2], a1c[3],
                         xf[1][2][0], xf[1][2][1], xf[1][2][2], xf[1][2][3], bw1.x, bw1.y);
            mma_tf32_acc(a0c[0], a0c[1], a0c[2], a0c[3],
                         xf[0][3][0], xf[0][3][1], xf[0][3][2], xf[0][3][3], bw1.z, bw1.w);
            mma_tf32_acc(a1c[0], a1c[1], a1c[2], a1c[3],
                         xf[1][3][0], xf[1][3][1], xf[1][3][2], xf[1][3][3], bw1.z, bw1.w);

            // q=2 (its 4,5) and q=3 (its 6,7)
            asm volatile("ld.shared.v4.b32 {%0,%1,%2,%3}, [%4];"
                         : "=r"(bw0.x), "=r"(bw0.y), "=r"(bw0.z), "=r"(bw0.w)
                         : "r"(baddr + 1024));
            asm volatile("ld.shared.v4.b32 {%0,%1,%2,%3}, [%4];"
                         : "=r"(bw1.x), "=r"(bw1.y), "=r"(bw1.z), "=r"(bw1.w)
                         : "r"(baddr + 1536));
            mma_tf32_acc(a0c[0], a0c[1], a0c[2], a0c[3],
                         xf[0][4][0], xf[0][4][1], xf[0][4][2], xf[0][4][3], bw0.x, bw0.y);
            mma_tf32_acc(a1c[0], a1c[1], a1c[2], a1c[3],
                         xf[1][4][0], xf[1][4][1], xf[1][4][2], xf[1][4][3], bw0.x, bw0.y);
            mma_tf32_acc(a0c[0], a0c[1], a0c[2], a0c[3],
                         xf[0][5][0], xf[0][5][1], xf[0][5][2], xf[0][5][3], bw0.z, bw0.w);
            mma_tf32_acc(a1c[0], a1c[1], a1c[2], a1c[3],
                         xf[1][5][0], xf[1][5][1], xf[1][5][2], xf[1][5][3], bw0.z, bw0.w);
            mma_tf32_acc(a0c[0], a0c[1], a0c[2], a0c[3],
                         xf[0][6][0], xf[0][6][1], xf[0][6][2], xf[0][6][3], bw1.x, bw1.y);
            mma_tf32_acc(a1c[0], a1c[1], a1c[2], a1c[3],
                         xf[1][6][0], xf[1][6][1], xf[1][6][2], xf[1][6][3], bw1.x, bw1.y);
            mma_tf32_acc(a0c[0], a0c[1], a0c[2], a0c[3],
                         xf[0][7][0], xf[0][7][1], xf[0][7][2], xf[0][7][3], bw1.z, bw1.w);
            mma_tf32_acc(a1c[0], a1c[1], a1c[2], a1c[3],
                         xf[1][7][0], xf[1][7][1], xf[1][7][2], xf[1][7][3], bw1.z, bw1.w);

            // fold S into master accumulators
            acc[0][nt][0] = fmaf(s00, a0c[0], acc[0][nt][0]);
            acc[0][nt][1] = fmaf(s00, a0c[1], acc[0][nt][1]);
            acc[0][nt][2] = fmaf(s01, a0c[2], acc[0][nt][2]);
            acc[0][nt][3] = fmaf(s01, a0c[3], acc[0][nt][3]);
            acc[1][nt][0] = fmaf(s10, a1c[0], acc[1][nt][0]);
            acc[1][nt][1] = fmaf(s10, a1c[1], acc[1][nt][1]);
            acc[1][nt][2] = fmaf(s11, a1c[2], acc[1][nt][2]);
            acc[1][nt][3] = fmaf(s11, a1c[3], acc[1][nt][3]);
        }
    }

    // ---- epilogue: fp32 store ----
#pragma unroll
    for (int mt = 0; mt < 2; ++mt) {
        const int t0 = bt0 + wm * 32 + mt * 16 + gid;
#pragma unroll
        for (int nt = 0; nt < 4; ++nt) {
            const int o = h * 64 + wn * 32 + nt * 8 + tig * 2;
            *(float2*)(out + (size_t)t0 * 1024 + o) =
                make_float2(acc[mt][nt][0], acc[mt][nt][1]);
            *(float2*)(out + (size_t)(t0 + 8) * 1024 + o) =
                make_float2(acc[mt][nt][2], acc[mt][nt][3]);
        }
    }
}

// ---------------------------------------------------------------------------
extern "C" void kernel_launch(void* const* d_in, const int* in_sizes, int n_in,
                              void* d_out, int out_size) {
    const float* x    = (const float*)d_in[0];   // [4,2048,1024]
    const float* wgt  = (const float*)d_in[1];   // [16,8,64,64]
    const float* diag = (const float*)d_in[2];   // [8,1024]
    const float* phi  = (const float*)d_in[3];   // [2048,8]
    float* out = (float*)d_out;                  // [4,2048,1024]

    const int main_smem = MAIN_SMEM_FLOATS * 4;
    cudaFuncSetAttribute(spectral_main_kernel,
                         cudaFuncAttributeMaxDynamicSharedMemorySize, main_smem);

    prep_w_kernel<<<128, 256>>>(wgt);
    scores_kernel<<<256, 256>>>(x, diag, phi);
    spectral_main_kernel<<<dim3(64, 16), 256, main_smem>>>(x, out);
}

// round 14
// speedup vs baseline: 1.5561x; 1.1265x over previous
#include <cuda_runtime.h>

// ============================================================================
// SpectralMoEHeads: out[bt, h*64+o] = sum_k S[bt,k] * sum_i x[bt,h*64+i]*W[h,k,i,o]
//   S[bt,k] = phi[bt%2048, k] + sum_i x[bt,i]*diag[k,i]
//
// R14 = R13 + cp.async STORE conflict fix:
//   thread copies float4 indices {tid, tid+256, tid+512, tid+768}
//   -> smem dst lane stride 16B (4-phase, conflict-free) instead of 64B
//   (16-way conflicted). Read layout unchanged from R13 (4-phase LDS.128).
// Prep kernel split into 256 blocks (o-halves; W re-read is L2-hot).
// ============================================================================

__device__ float g_scores[8192 * 8];
__device__ float4 wpack4[128 * 1024];   // [h*8+chunk][1024 float4] = 2 MB

__device__ __forceinline__ unsigned f2tf32(float f) {
    unsigned u;
    asm("cvt.rna.tf32.f32 %0, %1;" : "=r"(u) : "f"(f));
    return u;
}

__device__ __forceinline__ void mma_tf32_acc(float& c0, float& c1, float& c2, float& c3,
                                             unsigned a0, unsigned a1, unsigned a2, unsigned a3,
                                             unsigned b0, unsigned b1) {
    asm volatile(
        "mma.sync.aligned.m16n8k8.row.col.f32.tf32.tf32.f32 "
        "{%0,%1,%2,%3}, {%4,%5,%6,%7}, {%8,%9}, {%0,%1,%2,%3};\n"
        : "+f"(c0), "+f"(c1), "+f"(c2), "+f"(c3)
        : "r"(a0), "r"(a1), "r"(a2), "r"(a3), "r"(b0), "r"(b1));
}

__device__ __forceinline__ void mma_tf32_set(float& d0, float& d1, float& d2, float& d3,
                                             unsigned a0, unsigned a1, unsigned a2, unsigned a3,
                                             unsigned b0, unsigned b1) {
    asm volatile(
        "mma.sync.aligned.m16n8k8.row.col.f32.tf32.tf32.f32 "
        "{%0,%1,%2,%3}, {%4,%5,%6,%7}, {%8,%9}, {%10,%11,%12,%13};\n"
        : "=f"(d0), "=f"(d1), "=f"(d2), "=f"(d3)
        : "r"(a0), "r"(a1), "r"(a2), "r"(a3), "r"(b0), "r"(b1),
          "f"(0.f), "f"(0.f), "f"(0.f), "f"(0.f));
}

__device__ __forceinline__ void cp_async16(unsigned dst_smem, const void* src) {
    asm volatile("cp.async.cg.shared.global [%0], [%1], 16;\n"
                 :: "r"(dst_smem), "l"(src) : "memory");
}
__device__ __forceinline__ void cp_commit() {
    asm volatile("cp.async.commit_group;\n" ::: "memory");
}
template <int N>
__device__ __forceinline__ void cp_wait() {
    asm volatile("cp.async.wait_group %0;\n" :: "n"(N) : "memory");
}

// ---------------------------------------------------------------------------
// Kernel 0: pack W into fragment order (conflict-free read interleave).
// Per (h, chunk k): float4 index idx4 = ((wn*4+nt)*4 + q)*32 + lane, holding
// words j = q*4..q*4+3 with j = it*2+p :
//   W[h,k][ i = it*8 + tig + p*4 ][ o = wn*32 + nt*8 + gid ]
// Grid 256: block = (tile b, o-half); each block loads the full 16KB tile
// (L2-hot) and writes its 4 groups.
// ---------------------------------------------------------------------------
__global__ __launch_bounds__(256) void prep_w_kernel(const float* __restrict__ w)
{
    __shared__ float tile[4096];           // W[h,k][i][o] : 64 x 64
    const int b2  = blockIdx.x;            // 0..255
    const int b   = b2 >> 1;               // tile = h*8 + k
    const int hf  = b2 & 1;                // o-half
    const int tid = threadIdx.x;

    const float4* src = (const float4*)(w + (size_t)b * 4096);
#pragma unroll
    for (int it = 0; it < 4; ++it)
        ((float4*)tile)[tid + it * 256] = src[tid + it * 256];
    __syncthreads();

    const int grp  = hf * 4 + (tid >> 6);  // 0..7 (this block: 4 groups)
    const int q0   = ((tid >> 5) & 1) * 2; // 0 or 2
    const int lane = tid & 31;
    const int gid  = lane >> 2;
    const int tig  = lane & 3;
    const int wn   = grp >> 2;
    const int nt   = grp & 3;
    const int o    = wn * 32 + nt * 8 + gid;

#pragma unroll
    for (int qq = 0; qq < 2; ++qq) {
        const int q = q0 + qq;
        float v[4];
#pragma unroll
        for (int jj = 0; jj < 4; ++jj) {
            int j  = q * 4 + jj;
            int it = j >> 1, p = j & 1;
            v[jj] = tile[(it * 8 + tig + p * 4) * 64 + o];
        }
        wpack4[(size_t)b * 1024 + (grp * 4 + q) * 32 + lane] =
            make_float4(v[0], v[1], v[2], v[3]);
    }
}

// ---------------------------------------------------------------------------
// Kernel 1: scores (unchanged; near its DRAM floor)
// ---------------------------------------------------------------------------
__global__ __launch_bounds__(256) void scores_kernel(
    const float* __restrict__ x, const float* __restrict__ diag,
    const float* __restrict__ phi)
{
    __shared__ float4 diag_s[8 * 256];

    const int tid = threadIdx.x;
    for (int i = tid; i < 2048; i += 256) diag_s[i] = ((const float4*)diag)[i];
    __syncthreads();

    const int lane = tid & 31;
    const int w    = tid >> 5;
    const int t0   = (blockIdx.x * 8 + w) * 4;

    float acc[4][8];
#pragma unroll
    for (int t = 0; t < 4; ++t)
#pragma unroll
        for (int k = 0; k < 8; ++k) acc[t][k] = 0.f;

#pragma unroll
    for (int c = 0; c < 8; ++c) {
        float4 dv[8];
#pragma unroll
        for (int k = 0; k < 8; ++k) dv[k] = diag_s[k * 256 + c * 32 + lane];
#pragma unroll
        for (int t = 0; t < 4; ++t) {
            float4 xv = ((const float4*)x)[(size_t)(t0 + t) * 256 + c * 32 + lane];
#pragma unroll
            for (int k = 0; k < 8; ++k) {
                acc[t][k] = fmaf(xv.x, dv[k].x, acc[t][k]);
                acc[t][k] = fmaf(xv.y, dv[k].y, acc[t][k]);
                acc[t][k] = fmaf(xv.z, dv[k].z, acc[t][k]);
                acc[t][k] = fmaf(xv.w, dv[k].w, acc[t][k]);
            }
        }
    }

#pragma unroll
    for (int t = 0; t < 4; ++t)
#pragma unroll
        for (int k = 0; k < 8; ++k) {
            float v = acc[t][k];
            v += __shfl_xor_sync(0xffffffffu, v, 16);
            v += __shfl_xor_sync(0xffffffffu, v, 8);
            v += __shfl_xor_sync(0xffffffffu, v, 4);
            v += __shfl_xor_sync(0xffffffffu, v, 2);
            v += __shfl_xor_sync(0xffffffffu, v, 1);
            acc[t][k] = v;
        }

    if (lane == 0) {
#pragma unroll
        for (int t = 0; t < 4; ++t) {
            const int bt = t0 + t;
            float4 p0 = ((const float4*)phi)[(bt & 2047) * 2];
            float4 p1 = ((const float4*)phi)[(bt & 2047) * 2 + 1];
            float4 r0 = make_float4(acc[t][0] + p0.x, acc[t][1] + p0.y,
                                    acc[t][2] + p0.z, acc[t][3] + p0.w);
            float4 r1 = make_float4(acc[t][4] + p1.x, acc[t][5] + p1.y,
                                    acc[t][6] + p1.z, acc[t][7] + p1.w);
            ((float4*)g_scores)[bt * 2]     = r0;
            ((float4*)g_scores)[bt * 2 + 1] = r1;
        }
    }
}

// ---------------------------------------------------------------------------
// Kernel 2: main. CTA = (128-token tile, head), 256 threads = 8 warps
// (4m x 2n), warp tile 32x32, mma m16n8k8 tf32.
// smem floats: S_s[1152] | buf0[4096] | buf1[4096] | x_s[8704] (bufs 2,3 overlay)
// ---------------------------------------------------------------------------
#define SS_STRIDE   9
#define SMEM_SS     0
#define SMEM_BUF0   1152
#define SMEM_XS     (1152 + 2 * 4096)          // = 9344 (bufs 2,3 live here)
#define XS_STRIDE   68
#define MAIN_SMEM_FLOATS (SMEM_XS + 128 * XS_STRIDE)   // 18048 floats = 72192 B

__global__ __launch_bounds__(256, 2) void spectral_main_kernel(
    const float* __restrict__ x, float* __restrict__ out)
{
    extern __shared__ float sm[];
    float* S_s = sm + SMEM_SS;
    float* x_s = sm + SMEM_XS;
    const unsigned smem_u32 = (unsigned)__cvta_generic_to_shared(sm);
    const unsigned buf_base = smem_u32 + SMEM_BUF0 * 4;   // buf i at + i*16384 B

    const int tid  = threadIdx.x;
    const int h    = blockIdx.y;
    const int bt0  = blockIdx.x * 128;

    const int lane = tid & 31;
    const int wid  = tid >> 5;
    const int gid  = lane >> 2;   // 0..7
    const int tig  = lane & 3;    // 0..3
    const int wm   = wid & 3;     // m warp coord (x32)
    const int wn   = wid >> 2;    // n warp coord (x32)

    const float4* wsrc = wpack4 + (size_t)h * 8192;   // 8 chunks x 1024 float4

    // ---- prologue: cp.async W chunks 0,1 into bufs 0,1 (16B lane stride) ----
#pragma unroll
    for (int c = 0; c < 2; ++c) {
        const float4* src = wsrc + c * 1024 + tid;
        unsigned d = buf_base + c * 16384 + (unsigned)tid * 16;
        cp_async16(d,         src);
        cp_async16(d + 4096,  src + 256);
        cp_async16(d + 8192,  src + 512);
        cp_async16(d + 12288, src + 768);
        cp_commit();
    }

    // ---- stage x tile (128 x 64) into x_s (bufs 2,3 region — not yet used) ----
#pragma unroll
    for (int j = 0; j < 8; ++j) {
        int idx = tid + j * 256;
        int r = idx >> 4, c4 = idx & 15;
        float4 v = ((const float4*)x)[(size_t)(bt0 + r) * 256 + h * 16 + c4];
        float* d = x_s + r * XS_STRIDE + c4 * 4;
        d[0] = v.x; d[1] = v.y; d[2] = v.z; d[3] = v.w;
    }
    // ---- stage scores ----
#pragma unroll
    for (int j = 0; j < 4; ++j) {
        int idx = tid + j * 256;
        int r = idx >> 3, k = idx & 7;
        S_s[r * SS_STRIDE + k] = g_scores[(bt0 + r) * 8 + k];
    }
    __syncthreads();

    // ---- x fragments -> tf32 once ----
    unsigned xf[2][8][4];
#pragma unroll
    for (int mt = 0; mt < 2; ++mt) {
        const int t0 = wm * 32 + mt * 16 + gid;
        const int t1 = t0 + 8;
#pragma unroll
        for (int it = 0; it < 8; ++it) {
            const int i0 = it * 8 + tig;
            xf[mt][it][0] = f2tf32(x_s[t0 * XS_STRIDE + i0]);
            xf[mt][it][1] = f2tf32(x_s[t1 * XS_STRIDE + i0]);
            xf[mt][it][2] = f2tf32(x_s[t0 * XS_STRIDE + i0 + 4]);
            xf[mt][it][3] = f2tf32(x_s[t1 * XS_STRIDE + i0 + 4]);
        }
    }
    __syncthreads();   // all warps done reading x_s before buf2/3 prefetch

    float acc[2][4][4];
#pragma unroll
    for (int mt = 0; mt < 2; ++mt)
#pragma unroll
        for (int nt = 0; nt < 4; ++nt)
#pragma unroll
            for (int r = 0; r < 4; ++r) acc[mt][nt][r] = 0.f;

    // per-thread B base within a buffer: group (wn*4+nt) block is 2048 B;
    // within it, q blocks of 512 B, lane stride 16 B (4-phase LDS.128).
    const unsigned bthread = (unsigned)(wn * 4) * 2048 + (unsigned)lane * 16;

#pragma unroll 1
    for (int k = 0; k < 8; ++k) {
        if (k < 7) cp_wait<1>(); else cp_wait<0>();
        __syncthreads();   // single barrier per chunk

        // prefetch chunk k+2 into buf (k+2)&3 (last read in chunk k-2; all
        // warps are past the barrier of chunk k, hence done with k-2's reads)
        if (k + 2 < 8) {
            const float4* src = wsrc + (k + 2) * 1024 + tid;
            unsigned d = buf_base + ((k + 2) & 3) * 16384 + (unsigned)tid * 16;
            cp_async16(d,         src);
            cp_async16(d + 4096,  src + 256);
            cp_async16(d + 8192,  src + 512);
            cp_async16(d + 12288, src + 768);
            cp_commit();
        }

        const int tb = wm * 32 + gid;
        const float s00 = S_s[(tb)      * SS_STRIDE + k];
        const float s01 = S_s[(tb + 8)  * SS_STRIDE + k];
        const float s10 = S_s[(tb + 16) * SS_STRIDE + k];
        const float s11 = S_s[(tb + 24) * SS_STRIDE + k];

        const unsigned bbuf = buf_base + (k & 3) * 16384 + bthread;

#pragma unroll
        for (int nt = 0; nt < 4; ++nt) {
            const unsigned baddr = bbuf + (unsigned)nt * 2048;
            float a0c[4], a1c[4];
            uint4 bw0, bw1;

            // q=0 (its 0,1) and q=1 (its 2,3)
            asm volatile("ld.shared.v4.b32 {%0,%1,%2,%3}, [%4];"
                         : "=r"(bw0.x), "=r"(bw0.y), "=r"(bw0.z), "=r"(bw0.w)
                         : "r"(baddr));
            asm volatile("ld.shared.v4.b32 {%0,%1,%2,%3}, [%4];"
                         : "=r"(bw1.x), "=r"(bw1.y), "=r"(bw1.z), "=r"(bw1.w)
                         : "r"(baddr + 512));
            mma_tf32_set(a0c[0], a0c[1], a0c[2], a0c[3],
                         xf[0][0][0], xf[0][0][1], xf[0][0][2], xf[0][0][3], bw0.x, bw0.y);
            mma_tf32_set(a1c[0], a1c[1], a1c[2], a1c[3],
                         xf[1][0][0], xf[1][0][1], xf[1][0][2], xf[1][0][3], bw0.x, bw0.y);
            mma_tf32_acc(a0c[0], a0c[1], a0c[2], a0c[3],
                         xf[0][1][0], xf[0][1][1], xf[0][1][2], xf[0][1][3], bw0.z, bw0.w);
            mma_tf32_acc(a1c[0], a1c[1], a1c[2], a1c[3],
                         xf[1][1][0], xf[1][1][1], xf[1][1][2], xf[1][1][3], bw0.z, bw0.w);
            mma_tf32_acc(a0c[0], a0c[1], a0c[2], a0c[3],
                         xf[0][2][0], xf[0][2][1], xf[0][2][2], xf[0][2][3], bw1.x, bw1.y);
            mma_tf32_acc(a1c[0], a1c[1], a1c[2], a1c[3],
                         xf[1][2][0], xf[1][2][1], xf[1][2][2], xf[1][2][3], bw1.x, bw1.y);
            mma_tf32_acc(a0c[0], a0c[1], a0c[2], a0c[3],
                         xf[0][3][0], xf[0][3][1], xf[0][3][2], xf[0][3][3], bw1.z, bw1.w);
            mma_tf32_acc(a1c[0], a1c[1], a1c[2], a1c[3],
                         xf[1][3][0], xf[1][3][1], xf[1][3][2], xf[1][3][3], bw1.z, bw1.w);

            // q=2 (its 4,5) and q=3 (its 6,7)
            asm volatile("ld.shared.v4.b32 {%0,%1,%2,%3}, [%4];"
                         : "=r"(bw0.x), "=r"(bw0.y), "=r"(bw0.z), "=r"(bw0.w)
                         : "r"(baddr + 1024));
            asm volatile("ld.shared.v4.b32 {%0,%1,%2,%3}, [%4];"
                         : "=r"(bw1.x), "=r"(bw1.y), "=r"(bw1.z), "=r"(bw1.w)
                         : "r"(baddr + 1536));
            mma_tf32_acc(a0c[0], a0c[1], a0c[2], a0c[3],
                         xf[0][4][0], xf[0][4][1], xf[0][4][2], xf[0][4][3], bw0.x, bw0.y);
            mma_tf32_acc(a1c[0], a1c[1], a1c[2], a1c[3],
                         xf[1][4][0], xf[1][4][1], xf[1][4][2], xf[1][4][3], bw0.x, bw0.y);
            mma_tf32_acc(a0c[0], a0c[1], a0c[2], a0c[3],
                         xf[0][5][0], xf[0][5][1], xf[0][5][2], xf[0][5][3], bw0.z, bw0.w);
            mma_tf32_acc(a1c[0], a1c[1], a1c[2], a1c[3],
                         xf[1][5][0], xf[1][5][1], xf[1][5][2], xf[1][5][3], bw0.z, bw0.w);
            mma_tf32_acc(a0c[0], a0c[1], a0c[2], a0c[3],
                         xf[0][6][0], xf[0][6][1], xf[0][6][2], xf[0][6][3], bw1.x, bw1.y);
            mma_tf32_acc(a1c[0], a1c[1], a1c[2], a1c[3],
                         xf[1][6][0], xf[1][6][1], xf[1][6][2], xf[1][6][3], bw1.x, bw1.y);
            mma_tf32_acc(a0c[0], a0c[1], a0c[2], a0c[3],
                         xf[0][7][0], xf[0][7][1], xf[0][7][2], xf[0][7][3], bw1.z, bw1.w);
            mma_tf32_acc(a1c[0], a1c[1], a1c[2], a1c[3],
                         xf[1][7][0], xf[1][7][1], xf[1][7][2], xf[1][7][3], bw1.z, bw1.w);

            // fold S into master accumulators
            acc[0][nt][0] = fmaf(s00, a0c[0], acc[0][nt][0]);
            acc[0][nt][1] = fmaf(s00, a0c[1], acc[0][nt][1]);
            acc[0][nt][2] = fmaf(s01, a0c[2], acc[0][nt][2]);
            acc[0][nt][3] = fmaf(s01, a0c[3], acc[0][nt][3]);
            acc[1][nt][0] = fmaf(s10, a1c[0], acc[1][nt][0]);
            acc[1][nt][1] = fmaf(s10, a1c[1], acc[1][nt][1]);
            acc[1][nt][2] = fmaf(s11, a1c[2], acc[1][nt][2]);
            acc[1][nt][3] = fmaf(s11, a1c[3], acc[1][nt][3]);
        }
    }

    // ---- epilogue: fp32 store ----
#pragma unroll
    for (int mt = 0; mt < 2; ++mt) {
        const int t0 = bt0 + wm * 32 + mt * 16 + gid;
#pragma unroll
        for (int nt = 0; nt < 4; ++nt) {
            const int o = h * 64 + wn * 32 + nt * 8 + tig * 2;
            *(float2*)(out + (size_t)t0 * 1024 + o) =
                make_float2(acc[mt][nt][0], acc[mt][nt][1]);
            *(float2*)(out + (size_t)(t0 + 8) * 1024 + o) =
                make_float2(acc[mt][nt][2], acc[mt][nt][3]);
        }
    }
}

// ---------------------------------------------------------------------------
extern "C" void kernel_launch(void* const* d_in, const int* in_sizes, int n_in,
                              void* d_out, int out_size) {
    const float* x    = (const float*)d_in[0];   // [4,2048,1024]
    const float* wgt  = (const float*)d_in[1];   // [16,8,64,64]
    const float* diag = (const float*)d_in[2];   // [8,1024]
    const float* phi  = (const float*)d_in[3];   // [2048,8]
    float* out = (float*)d_out;                  // [4,2048,1024]

    const int main_smem = MAIN_SMEM_FLOATS * 4;
    cudaFuncSetAttribute(spectral_main_kernel,
                         cudaFuncAttributeMaxDynamicSharedMemorySize, main_smem);

    prep_w_kernel<<<256, 256>>>(wgt);
    scores_kernel<<<256, 256>>>(x, diag, phi);
    spectral_main_kernel<<<dim3(64, 16), 256, main_smem>>>(x, out);
}

// round 15
// speedup vs baseline: 1.6168x; 1.0390x over previous
#include <cuda_runtime.h>

// ============================================================================
// SpectralMoEHeads: out[bt, h*64+o] = sum_k S[bt,k] * sum_i x[bt,h*64+i]*W[h,k,i,o]
//   S[bt,k] = phi[bt%2048, k] + sum_i x[bt,i]*diag[k,i]
//
// R15 = R14 +
//  - prep_w and scores FUSED into one kernel (512 blocks, branch on blockIdx):
//    they are independent; running them concurrently removes ~5us of
//    serialized launch time.
//  - main kernel: x_s gets its own smem region (no buf-2/3 overlay), dropping
//    the second prologue barrier; W pipeline deepened to prefetch distance 3
//    (chunks 0..2 staged upfront, steady-state cp.async slack = 3 chunks).
// ============================================================================

__device__ float g_scores[8192 * 8];
__device__ float4 wpack4[128 * 1024];   // [h*8+chunk][1024 float4] = 2 MB

__device__ __forceinline__ unsigned f2tf32(float f) {
    unsigned u;
    asm("cvt.rna.tf32.f32 %0, %1;" : "=r"(u) : "f"(f));
    return u;
}

__device__ __forceinline__ void mma_tf32_acc(float& c0, float& c1, float& c2, float& c3,
                                             unsigned a0, unsigned a1, unsigned a2, unsigned a3,
                                             unsigned b0, unsigned b1) {
    asm volatile(
        "mma.sync.aligned.m16n8k8.row.col.f32.tf32.tf32.f32 "
        "{%0,%1,%2,%3}, {%4,%5,%6,%7}, {%8,%9}, {%0,%1,%2,%3};\n"
        : "+f"(c0), "+f"(c1), "+f"(c2), "+f"(c3)
        : "r"(a0), "r"(a1), "r"(a2), "r"(a3), "r"(b0), "r"(b1));
}

__device__ __forceinline__ void mma_tf32_set(float& d0, float& d1, float& d2, float& d3,
                                             unsigned a0, unsigned a1, unsigned a2, unsigned a3,
                                             unsigned b0, unsigned b1) {
    asm volatile(
        "mma.sync.aligned.m16n8k8.row.col.f32.tf32.tf32.f32 "
        "{%0,%1,%2,%3}, {%4,%5,%6,%7}, {%8,%9}, {%10,%11,%12,%13};\n"
        : "=f"(d0), "=f"(d1), "=f"(d2), "=f"(d3)
        : "r"(a0), "r"(a1), "r"(a2), "r"(a3), "r"(b0), "r"(b1),
          "f"(0.f), "f"(0.f), "f"(0.f), "f"(0.f));
}

__device__ __forceinline__ void cp_async16(unsigned dst_smem, const void* src) {
    asm volatile("cp.async.cg.shared.global [%0], [%1], 16;\n"
                 :: "r"(dst_smem), "l"(src) : "memory");
}
__device__ __forceinline__ void cp_commit() {
    asm volatile("cp.async.commit_group;\n" ::: "memory");
}
template <int N>
__device__ __forceinline__ void cp_wait() {
    asm volatile("cp.async.wait_group %0;\n" :: "n"(N) : "memory");
}

// ---------------------------------------------------------------------------
// Fused kernel 0: blocks [0,256) pack W; blocks [256,512) compute scores.
// Both halves are independent and fill the chip concurrently.
// ---------------------------------------------------------------------------
__global__ __launch_bounds__(256) void prep_scores_kernel(
    const float* __restrict__ x, const float* __restrict__ w,
    const float* __restrict__ diag, const float* __restrict__ phi)
{
    __shared__ float shbuf[8 * 1024];      // 32 KB: prep uses 16KB, scores 32KB
    const int tid = threadIdx.x;

    if (blockIdx.x < 256) {
        // ---------------- W packing (fragment order, conflict-free) --------
        float* tile = shbuf;               // 64 x 64 f32 = 16 KB
        const int b2  = blockIdx.x;
        const int b   = b2 >> 1;           // tile = h*8 + k
        const int hf  = b2 & 1;            // o-half

        const float4* src = (const float4*)(w + (size_t)b * 4096);
#pragma unroll
        for (int it = 0; it < 4; ++it)
            ((float4*)tile)[tid + it * 256] = src[tid + it * 256];
        __syncthreads();

        const int grp  = hf * 4 + (tid >> 6);  // 0..7
        const int q0   = ((tid >> 5) & 1) * 2;
        const int lane = tid & 31;
        const int gid  = lane >> 2;
        const int tig  = lane & 3;
        const int wn   = grp >> 2;
        const int nt   = grp & 3;
        const int o    = wn * 32 + nt * 8 + gid;

#pragma unroll
        for (int qq = 0; qq < 2; ++qq) {
            const int q = q0 + qq;
            float v[4];
#pragma unroll
            for (int jj = 0; jj < 4; ++jj) {
                int j  = q * 4 + jj;
                int it = j >> 1, p = j & 1;
                v[jj] = tile[(it * 8 + tig + p * 4) * 64 + o];
            }
            wpack4[(size_t)b * 1024 + (grp * 4 + q) * 32 + lane] =
                make_float4(v[0], v[1], v[2], v[3]);
        }
    } else {
        // ---------------- scores -------------------------------------------
        float4* diag_s = (float4*)shbuf;   // 8 * 256 float4 = 32 KB
        for (int i = tid; i < 2048; i += 256) diag_s[i] = ((const float4*)diag)[i];
        __syncthreads();

        const int lane = tid & 31;
        const int wrp  = tid >> 5;
        const int t0   = ((blockIdx.x - 256) * 8 + wrp) * 4;

        float acc[4][8];
#pragma unroll
        for (int t = 0; t < 4; ++t)
#pragma unroll
            for (int k = 0; k < 8; ++k) acc[t][k] = 0.f;

#pragma unroll
        for (int c = 0; c < 8; ++c) {
            float4 dv[8];
#pragma unroll
            for (int k = 0; k < 8; ++k) dv[k] = diag_s[k * 256 + c * 32 + lane];
#pragma unroll
            for (int t = 0; t < 4; ++t) {
                float4 xv = ((const float4*)x)[(size_t)(t0 + t) * 256 + c * 32 + lane];
#pragma unroll
                for (int k = 0; k < 8; ++k) {
                    acc[t][k] = fmaf(xv.x, dv[k].x, acc[t][k]);
                    acc[t][k] = fmaf(xv.y, dv[k].y, acc[t][k]);
                    acc[t][k] = fmaf(xv.z, dv[k].z, acc[t][k]);
                    acc[t][k] = fmaf(xv.w, dv[k].w, acc[t][k]);
                }
            }
        }

#pragma unroll
        for (int t = 0; t < 4; ++t)
#pragma unroll
            for (int k = 0; k < 8; ++k) {
                float v = acc[t][k];
                v += __shfl_xor_sync(0xffffffffu, v, 16);
                v += __shfl_xor_sync(0xffffffffu, v, 8);
                v += __shfl_xor_sync(0xffffffffu, v, 4);
                v += __shfl_xor_sync(0xffffffffu, v, 2);
                v += __shfl_xor_sync(0xffffffffu, v, 1);
                acc[t][k] = v;
            }

        if (lane == 0) {
#pragma unroll
            for (int t = 0; t < 4; ++t) {
                const int bt = t0 + t;
                float4 p0 = ((const float4*)phi)[(bt & 2047) * 2];
                float4 p1 = ((const float4*)phi)[(bt & 2047) * 2 + 1];
                float4 r0 = make_float4(acc[t][0] + p0.x, acc[t][1] + p0.y,
                                        acc[t][2] + p0.z, acc[t][3] + p0.w);
                float4 r1 = make_float4(acc[t][4] + p1.x, acc[t][5] + p1.y,
                                        acc[t][6] + p1.z, acc[t][7] + p1.w);
                ((float4*)g_scores)[bt * 2]     = r0;
                ((float4*)g_scores)[bt * 2 + 1] = r1;
            }
        }
    }
}

// ---------------------------------------------------------------------------
// Main kernel: CTA = (128-token tile, head), 256 threads = 8 warps (4m x 2n),
// warp tile 32x32, mma m16n8k8 tf32.
// smem floats: S_s[1152] | buf0..3[4x4096] | x_s[8704]  (no overlay)
//   = 26240 floats = 104960 B  -> 2 CTAs/SM (209920 <= 228KB)
// ---------------------------------------------------------------------------
#define SS_STRIDE   9
#define SMEM_SS     0
#define SMEM_BUF0   1152
#define SMEM_XS     (1152 + 4 * 4096)          // x_s after the 4 W buffers
#define XS_STRIDE   68
#define MAIN_SMEM_FLOATS (SMEM_XS + 128 * XS_STRIDE)   // 26240 floats

__global__ __launch_bounds__(256, 2) void spectral_main_kernel(
    const float* __restrict__ x, float* __restrict__ out)
{
    extern __shared__ float sm[];
    float* S_s = sm + SMEM_SS;
    float* x_s = sm + SMEM_XS;
    const unsigned smem_u32 = (unsigned)__cvta_generic_to_shared(sm);
    const unsigned buf_base = smem_u32 + SMEM_BUF0 * 4;   // buf i at + i*16384 B

    const int tid  = threadIdx.x;
    const int h    = blockIdx.y;
    const int bt0  = blockIdx.x * 128;

    const int lane = tid & 31;
    const int wid  = tid >> 5;
    const int gid  = lane >> 2;   // 0..7
    const int tig  = lane & 3;    // 0..3
    const int wm   = wid & 3;     // m warp coord (x32)
    const int wn   = wid >> 2;    // n warp coord (x32)

    const float4* wsrc = wpack4 + (size_t)h * 8192;   // 8 chunks x 1024 float4

    // ---- prologue: cp.async W chunks 0,1,2 into bufs 0,1,2 (16B lane stride) ----
#pragma unroll
    for (int c = 0; c < 3; ++c) {
        const float4* src = wsrc + c * 1024 + tid;
        unsigned d = buf_base + c * 16384 + (unsigned)tid * 16;
        cp_async16(d,         src);
        cp_async16(d + 4096,  src + 256);
        cp_async16(d + 8192,  src + 512);
        cp_async16(d + 12288, src + 768);
        cp_commit();
    }

    // ---- stage x tile (128 x 64) into x_s ----
#pragma unroll
    for (int j = 0; j < 8; ++j) {
        int idx = tid + j * 256;
        int r = idx >> 4, c4 = idx & 15;
        float4 v = ((const float4*)x)[(size_t)(bt0 + r) * 256 + h * 16 + c4];
        float* d = x_s + r * XS_STRIDE + c4 * 4;
        d[0] = v.x; d[1] = v.y; d[2] = v.z; d[3] = v.w;
    }
    // ---- stage scores ----
#pragma unroll
    for (int j = 0; j < 4; ++j) {
        int idx = tid + j * 256;
        int r = idx >> 3, k = idx & 7;
        S_s[r * SS_STRIDE + k] = g_scores[(bt0 + r) * 8 + k];
    }
    __syncthreads();

    // ---- x fragments -> tf32 once (x_s is dedicated; no further barrier) ----
    unsigned xf[2][8][4];
#pragma unroll
    for (int mt = 0; mt < 2; ++mt) {
        const int t0 = wm * 32 + mt * 16 + gid;
        const int t1 = t0 + 8;
#pragma unroll
        for (int it = 0; it < 8; ++it) {
            const int i0 = it * 8 + tig;
            xf[mt][it][0] = f2tf32(x_s[t0 * XS_STRIDE + i0]);
            xf[mt][it][1] = f2tf32(x_s[t1 * XS_STRIDE + i0]);
            xf[mt][it][2] = f2tf32(x_s[t0 * XS_STRIDE + i0 + 4]);
            xf[mt][it][3] = f2tf32(x_s[t1 * XS_STRIDE + i0 + 4]);
        }
    }

    float acc[2][4][4];
#pragma unroll
    for (int mt = 0; mt < 2; ++mt)
#pragma unroll
        for (int nt = 0; nt < 4; ++nt)
#pragma unroll
            for (int r = 0; r < 4; ++r) acc[mt][nt][r] = 0.f;

    // per-thread B base within a buffer: group (wn*4+nt) block is 2048 B;
    // within it, q blocks of 512 B, lane stride 16 B (4-phase LDS.128).
    const unsigned bthread = (unsigned)(wn * 4) * 2048 + (unsigned)lane * 16;

#pragma unroll 1
    for (int k = 0; k < 8; ++k) {
        // chunk k resident: groups newer than k outstanding = 2 (k<=5), 1 (k=6), 0 (k=7)
        if (k <= 5)      cp_wait<2>();
        else if (k == 6) cp_wait<1>();
        else             cp_wait<0>();
        __syncthreads();   // single barrier per chunk

        // prefetch chunk k+3 into buf (k+3)&3 = (k-1)&3 (all warps are past
        // the barrier of chunk k, hence done with chunk k-1's reads)
        if (k + 3 < 8) {
            const float4* src = wsrc + (k + 3) * 1024 + tid;
            unsigned d = buf_base + ((k + 3) & 3) * 16384 + (unsigned)tid * 16;
            cp_async16(d,         src);
            cp_async16(d + 4096,  src + 256);
            cp_async16(d + 8192,  src + 512);
            cp_async16(d + 12288, src + 768);
            cp_commit();
        }

        const int tb = wm * 32 + gid;
        const float s00 = S_s[(tb)      * SS_STRIDE + k];
        const float s01 = S_s[(tb + 8)  * SS_STRIDE + k];
        const float s10 = S_s[(tb + 16) * SS_STRIDE + k];
        const float s11 = S_s[(tb + 24) * SS_STRIDE + k];

        const unsigned bbuf = buf_base + (k & 3) * 16384 + bthread;

#pragma unroll
        for (int nt = 0; nt < 4; ++nt) {
            const unsigned baddr = bbuf + (unsigned)nt * 2048;
            float a0c[4], a1c[4];
            uint4 bw0, bw1;

            // q=0 (its 0,1) and q=1 (its 2,3)
            asm volatile("ld.shared.v4.b32 {%0,%1,%2,%3}, [%4];"
                         : "=r"(bw0.x), "=r"(bw0.y), "=r"(bw0.z), "=r"(bw0.w)
                         : "r"(baddr));
            asm volatile("ld.shared.v4.b32 {%0,%1,%2,%3}, [%4];"
                         : "=r"(bw1.x), "=r"(bw1.y), "=r"(bw1.z), "=r"(bw1.w)
                         : "r"(baddr + 512));
            mma_tf32_set(a0c[0], a0c[1], a0c[2], a0c[3],
                         xf[0][0][0], xf[0][0][1], xf[0][0][2], xf[0][0][3], bw0.x, bw0.y);
            mma_tf32_set(a1c[0], a1c[1], a1c[2], a1c[3],
                         xf[1][0][0], xf[1][0][1], xf[1][0][2], xf[1][0][3], bw0.x, bw0.y);
            mma_tf32_acc(a0c[0], a0c[1], a0c[2], a0c[3],
                         xf[0][1][0], xf[0][1][1], xf[0][1][2], xf[0][1][3], bw0.z, bw0.w);
            mma_tf32_acc(a1c[0], a1c[1], a1c[2], a1c[3],
                         xf[1][1][0], xf[1][1][1], xf[1][1][2], xf[1][1][3], bw0.z, bw0.w);
            mma_tf32_acc(a0c[0], a0c[1], a0c[2], a0c[3],
                         xf[0][2][0], xf[0][2][1], xf[0][2][2], xf[0][2][3], bw1.x, bw1.y);
            mma_tf32_acc(a1c[0], a1c[1], a1c[2], a1c[3],
                         xf[1][2][0], xf[1][2][1], xf[1][2][2], xf[1][2][3], bw1.x, bw1.y);
            mma_tf32_acc(a0c[0], a0c[1], a0c[2], a0c[3],
                         xf[0][3][0], xf[0][3][1], xf[0][3][2], xf[0][3][3], bw1.z, bw1.w);
            mma_tf32_acc(a1c[0], a1c[1], a1c[2], a1c[3],
                         xf[1][3][0], xf[1][3][1], xf[1][3][2], xf[1][3][3], bw1.z, bw1.w);

            // q=2 (its 4,5) and q=3 (its 6,7)
            asm volatile("ld.shared.v4.b32 {%0,%1,%2,%3}, [%4];"
                         : "=r"(bw0.x), "=r"(bw0.y), "=r"(bw0.z), "=r"(bw0.w)
                         : "r"(baddr + 1024));
            asm volatile("ld.shared.v4.b32 {%0,%1,%2,%3}, [%4];"
                         : "=r"(bw1.x), "=r"(bw1.y), "=r"(bw1.z), "=r"(bw1.w)
                         : "r"(baddr + 1536));
            mma_tf32_acc(a0c[0], a0c[1], a0c[2], a0c[3],
                         xf[0][4][0], xf[0][4][1], xf[0][4][2], xf[0][4][3], bw0.x, bw0.y);
            mma_tf32_acc(a1c[0], a1c[1], a1c[2], a1c[3],
                         xf[1][4][0], xf[1][4][1], xf[1][4][2], xf[1][4][3], bw0.x, bw0.y);
            mma_tf32_acc(a0c[0], a0c[1], a0c[2], a0c[3],
                         xf[0][5][0], xf[0][5][1], xf[0][5][2], xf[0][5][3], bw0.z, bw0.w);
            mma_tf32_acc(a1c[0], a1c[1], a1c[2], a1c[3],
                         xf[1][5][0], xf[1][5][1], xf[1][5][2], xf[1][5][3], bw0.z, bw0.w);
            mma_tf32_acc(a0c[0], a0c[1], a0c[2], a0c[3],
                         xf[0][6][0], xf[0][6][1], xf[0][6][2], xf[0][6][3], bw1.x, bw1.y);
            mma_tf32_acc(a1c[0], a1c[1], a1c[2], a1c[3],
                         xf[1][6][0], xf[1][6][1], xf[1][6][2], xf[1][6][3], bw1.x, bw1.y);
            mma_tf32_acc(a0c[0], a0c[1], a0c[2], a0c[3],
                         xf[0][7][0], xf[0][7][1], xf[0][7][2], xf[0][7][3], bw1.z, bw1.w);
            mma_tf32_acc(a1c[0], a1c[1], a1c[2], a1c[3],
                         xf[1][7][0], xf[1][7][1], xf[1][7][2], xf[1][7][3], bw1.z, bw1.w);

            // fold S into master accumulators
            acc[0][nt][0] = fmaf(s00, a0c[0], acc[0][nt][0]);
            acc[0][nt][1] = fmaf(s00, a0c[1], acc[0][nt][1]);
            acc[0][nt][2] = fmaf(s01, a0c[2], acc[0][nt][2]);
            acc[0][nt][3] = fmaf(s01, a0c[3], acc[0][nt][3]);
            acc[1][nt][0] = fmaf(s10, a1c[0], acc[1][nt][0]);
            acc[1][nt][1] = fmaf(s10, a1c[1], acc[1][nt][1]);
            acc[1][nt][2] = fmaf(s11, a1c[2], acc[1][nt][2]);
            acc[1][nt][3] = fmaf(s11, a1c[3], acc[1][nt][3]);
        }
    }

    // ---- epilogue: fp32 store ----
#pragma unroll
    for (int mt = 0; mt < 2; ++mt) {
        const int t0 = bt0 + wm * 32 + mt * 16 + gid;
#pragma unroll
        for (int nt = 0; nt < 4; ++nt) {
            const int o = h * 64 + wn * 32 + nt * 8 + tig * 2;
            *(float2*)(out + (size_t)t0 * 1024 + o) =
                make_float2(acc[mt][nt][0], acc[mt][nt][1]);
            *(float2*)(out + (size_t)(t0 + 8) * 1024 + o) =
                make_float2(acc[mt][nt][2], acc[mt][nt][3]);
        }
    }
}

// ---------------------------------------------------------------------------
extern "C" void kernel_launch(void* const* d_in, const int* in_sizes, int n_in,
                              void* d_out, int out_size) {
    const float* x    = (const float*)d_in[0];   // [4,2048,1024]
    const float* wgt  = (const float*)d_in[1];   // [16,8,64,64]
    const float* diag = (const float*)d_in[2];   // [8,1024]
    const float* phi  = (const float*)d_in[3];   // [2048,8]
    float* out = (float*)d_out;                  // [4,2048,1024]

    const int main_smem = MAIN_SMEM_FLOATS * 4;
    cudaFuncSetAttribute(spectral_main_kernel,
                         cudaFuncAttributeMaxDynamicSharedMemorySize, main_smem);

    prep_scores_kernel<<<512, 256>>>(x, wgt, diag, phi);
    spectral_main_kernel<<<dim3(64, 16), 256, main_smem>>>(x, out);
}